// round 2
// baseline (speedup 1.0000x reference)
#include <cuda_runtime.h>
#include <cuda_bf16.h>

// Problem constants
#define BB 2        // batch
#define SS 256      // seq
#define DD 256      // d_model
#define DFF 1024
#define HH 256      // hidden of pairwise MLP
#define LL 2        // layers
#define ROWS (BB*SS)   // 512

// ---------------- scratch (device globals; no allocation allowed) -------------
#define OFF_H     0
#define OFF_QKV   131072
#define OFF_QA    262144
#define OFF_QB    393216   /* must be OFF_QA + ROWS*HH for fused qa/qb */
#define OFF_S1    524288
#define OFF_ATTN  655360
#define OFF_AO    786432
#define OFF_PROJ  917504
#define OFF_O1    1048576
#define OFF_F1    1179648  /* ROWS*DFF = 524288 */
#define OFF_F2    1703936  /* 4 split-K partials, 4*ROWS*DD = 524288 */
#define BUF_TOTAL 2228224

__device__ float g_buf[BUF_TOTAL];
__device__ int   g_idx[ROWS];

// ---------------- cumsum of (1-mask) -> positional index ---------------------
__global__ void scan_kernel(const float* __restrict__ mask, int* __restrict__ idx) {
    int b = threadIdx.x;
    if (b < BB) {
        float c = 0.f;
        for (int s = 0; s < SS; s++) {
            c += 1.0f - mask[b * SS + s];
            idx[b * SS + s] = (int)c;
        }
    }
}

// ---------------- embedding: (bits@W + b)*16 + pos_enc[idx] -------------------
__global__ void embed_kernel(const int* __restrict__ x,
                             const float* __restrict__ emb_W,
                             const float* __restrict__ emb_b,
                             const float* __restrict__ pos_enc,
                             const int* __restrict__ idx,
                             const int* __restrict__ use_pos,
                             float* __restrict__ h) {
    int bs = blockIdx.x;      // 0..511
    int d  = threadIdx.x;     // 0..255
    int val = x[bs];
    float acc = emb_b[d];
    #pragma unroll
    for (int k = 0; k < 16; k++) {
        if ((val >> k) & 1) acc += emb_W[k * DD + d];
    }
    acc *= 16.0f;  // sqrt(256)
    if (use_pos[0]) acc += pos_enc[idx[bs] * DD + d];
    h[bs * DD + d] = acc;
}

// ---------------- templated tiled GEMM: C = A(MxK,lda) @ B(KxN) [+ bias] ------
// 256 threads, BK=16, 16x16 thread grid, microtile (BM/16)x(BN/16).
// z (blockIdx.z) applies strides sA (elements), sB, sC. Bias applied only z==0.
template<int BM, int BN>
__global__ __launch_bounds__(256) void gemm_t(
    const float* __restrict__ A, const float* __restrict__ B,
    const float* __restrict__ bias, float* __restrict__ C,
    int M, int N, int K, int lda,
    long long sA, long long sB, long long sC, int relu)
{
    constexpr int MI = BM / 16;
    constexpr int NI = BN / 16;
    constexpr int EA = BM / 16;        // A elems per thread (along k)
    constexpr int TA = 16 / EA;        // threads covering one A row's k-slab
    constexpr int EB = BN / 16;        // B elems per thread (along n)
    constexpr int TB = BN / EB;        // threads per B row

    __shared__ float As[16][BM];
    __shared__ float Bs[16][BN];

    int tid = threadIdx.x;
    int bm = blockIdx.y, bn = blockIdx.x, z = blockIdx.z;
    A += (long long)z * sA; B += (long long)z * sB; C += (long long)z * sC;

    int aRow = tid / TA;
    int aK   = (tid % TA) * EA;
    int bRow = tid / TB;
    int bCol = (tid % TB) * EB;
    int ty = tid >> 4, tx = tid & 15;

    float acc[MI][NI];
    #pragma unroll
    for (int i = 0; i < MI; i++)
        #pragma unroll
        for (int j = 0; j < NI; j++) acc[i][j] = 0.f;

    const float* Ag = A + (long long)(bm * BM + aRow) * lda + aK;
    const float* Bg = B + (long long)bRow * N + bn * BN + bCol;

    for (int kt = 0; kt < K; kt += 16) {
        #pragma unroll
        for (int e = 0; e < EA; e++)
            As[aK + e][aRow] = Ag[kt + e];
        #pragma unroll
        for (int e = 0; e < EB; e++)
            Bs[bRow][bCol + e] = Bg[(long long)kt * N + e];
        __syncthreads();
        #pragma unroll
        for (int k = 0; k < 16; k++) {
            float av[MI], bv[NI];
            #pragma unroll
            for (int i = 0; i < MI; i++) av[i] = As[k][ty * MI + i];
            #pragma unroll
            for (int j = 0; j < NI; j++) bv[j] = Bs[k][tx * NI + j];
            #pragma unroll
            for (int i = 0; i < MI; i++)
                #pragma unroll
                for (int j = 0; j < NI; j++)
                    acc[i][j] += av[i] * bv[j];
        }
        __syncthreads();
    }

    #pragma unroll
    for (int j = 0; j < NI; j++) {
        int col = bn * BN + tx * NI + j;
        float bv = (bias && z == 0) ? bias[col] : 0.f;
        #pragma unroll
        for (int i = 0; i < MI; i++) {
            int row = bm * BM + ty * MI + i;
            float r = acc[i][j] + bv;
            if (relu) r = fmaxf(r, 0.f);
            C[(long long)row * N + col] = r;
        }
    }
}

// ---------------- pairwise-MLP similarity: s1[i,j] = sum_h w2*relu(qa_i+qb_j+b1)
// Grid (8,8,2), 64 threads, 32x32 tile, 4x4 micro. b1 folded into Qb tile load.
__global__ __launch_bounds__(64) void sim_kernel(
    const float* __restrict__ qa, const float* __restrict__ qb,
    const float* __restrict__ b1, const float* __restrict__ w2,
    float* __restrict__ s1)
{
    int b  = blockIdx.z;
    int i0 = blockIdx.y * 32;
    int j0 = blockIdx.x * 32;
    __shared__ float Qa[32][33];  // [h][i]
    __shared__ float Qb[32][33];  // [h][j]
    __shared__ float W[32];
    int tid = threadIdx.x;        // 0..63
    int ty = tid >> 3, tx = tid & 7;

    float acc[4][4];
    #pragma unroll
    for (int i = 0; i < 4; i++)
        #pragma unroll
        for (int j = 0; j < 4; j++) acc[i][j] = 0.f;

    const float* A  = qa + (long long)(b * SS + i0) * HH;
    const float* Bq = qb + (long long)(b * SS + j0) * HH;

    for (int hc = 0; hc < HH; hc += 32) {
        #pragma unroll
        for (int r = 0; r < 16; r++) {
            int e  = r * 64 + tid;
            int ii = e >> 5, kk = e & 31;
            Qa[kk][ii] = A[ii * HH + hc + kk];
            Qb[kk][ii] = Bq[ii * HH + hc + kk] + b1[hc + kk];
        }
        if (tid < 32) W[tid] = w2[hc + tid];
        __syncthreads();
        #pragma unroll 8
        for (int k = 0; k < 32; k++) {
            float w = W[k];
            float av[4], bv[4];
            #pragma unroll
            for (int i = 0; i < 4; i++) av[i] = Qa[k][ty * 4 + i];
            #pragma unroll
            for (int j = 0; j < 4; j++) bv[j] = Qb[k][tx * 4 + j];
            #pragma unroll
            for (int i = 0; i < 4; i++)
                #pragma unroll
                for (int j = 0; j < 4; j++)
                    acc[i][j] += w * fmaxf(av[i] + bv[j], 0.f);
        }
        __syncthreads();
    }

    #pragma unroll
    for (int i = 0; i < 4; i++)
        #pragma unroll
        for (int j = 0; j < 4; j++)
            s1[(long long)b * SS * SS + (i0 + ty * 4 + i) * SS + (j0 + tx * 4 + j)] = acc[i][j];
}

// ---------------- softmax over (s1 + s1^T + mask*-1e9) ------------------------
// +2*nn_b2 is row-uniform -> cancels in softmax.
__global__ __launch_bounds__(256) void softmax_kernel(
    const float* __restrict__ s1, const float* __restrict__ mask,
    float* __restrict__ attn)
{
    int i = blockIdx.x, b = blockIdx.y, j = threadIdx.x;
    const float* S = s1 + (long long)b * SS * SS;
    float v = S[i * SS + j] + S[j * SS + i] + mask[b * SS + j] * -1e9f;
    __shared__ float red[SS];
    red[j] = v; __syncthreads();
    for (int st = 128; st > 0; st >>= 1) {
        if (j < st) red[j] = fmaxf(red[j], red[j + st]);
        __syncthreads();
    }
    float m = red[0]; __syncthreads();
    float e = expf(v - m);
    red[j] = e; __syncthreads();
    for (int st = 128; st > 0; st >>= 1) {
        if (j < st) red[j] += red[j + st];
        __syncthreads();
    }
    attn[(long long)b * SS * SS + i * SS + j] = e / red[0];
}

// ---------------- residual add (+ split-K partial sum) + layernorm ------------
__global__ __launch_bounds__(256) void add_ln_kernel(
    const float* __restrict__ x, const float* __restrict__ y,
    int nparts, long long pstride,
    const float* __restrict__ g, const float* __restrict__ bt,
    float* __restrict__ out)
{
    int row = blockIdx.x, t = threadIdx.x;
    long long e = (long long)row * DD + t;
    float v = x[e];
    for (int p = 0; p < nparts; p++) v += y[p * pstride + e];  // RES=1, ALT=1
    __shared__ float red[DD];
    red[t] = v; __syncthreads();
    for (int st = 128; st > 0; st >>= 1) {
        if (t < st) red[t] += red[t + st];
        __syncthreads();
    }
    float mu = red[0] * (1.0f / DD); __syncthreads();
    float d = v - mu;
    red[t] = d * d; __syncthreads();
    for (int st = 128; st > 0; st >>= 1) {
        if (t < st) red[t] += red[t + st];
        __syncthreads();
    }
    float var = red[0] * (1.0f / DD);
    out[e] = d * rsqrtf(var + 1e-6f) * g[t] + bt[t];
}

// ---------------- host orchestration ------------------------------------------
extern "C" void kernel_launch(void* const* d_in, const int* in_sizes, int n_in,
                              void* d_out, int out_size) {
    const int*   x       = (const int*)d_in[0];
    const float* mask    = (const float*)d_in[1];
    const int*   use_pos = (const int*)d_in[3];
    const float* pos_enc = (const float*)d_in[4];
    const float* emb_W   = (const float*)d_in[5];
    const float* emb_b   = (const float*)d_in[6];
    const float* nn_W1   = (const float*)d_in[7];
    const float* nn_b1   = (const float*)d_in[8];
    const float* nn_W2   = (const float*)d_in[9];
    const float* w_W     = (const float*)d_in[11];
    const float* w_b     = (const float*)d_in[12];
    const float* out_W   = (const float*)d_in[13];
    const float* out_b   = (const float*)d_in[14];
    const float* ffn_W1  = (const float*)d_in[15];
    const float* ffn_b1  = (const float*)d_in[16];
    const float* ffn_W2  = (const float*)d_in[17];
    const float* ffn_b2  = (const float*)d_in[18];
    const float* ln1_g   = (const float*)d_in[19];
    const float* ln1_b   = (const float*)d_in[20];
    const float* ln2_g   = (const float*)d_in[21];
    const float* ln2_b   = (const float*)d_in[22];
    float* out = (float*)d_out;

    float* buf = nullptr;
    int* idx = nullptr;
    cudaGetSymbolAddress((void**)&buf, g_buf);
    cudaGetSymbolAddress((void**)&idx, g_idx);

    float* h    = buf + OFF_H;
    float* qkv  = buf + OFF_QKV;
    float* qa   = buf + OFF_QA;   // qb = qa + ROWS*HH (fused dual GEMM)
    float* s1   = buf + OFF_S1;
    float* attn = buf + OFF_ATTN;
    float* ao   = buf + OFF_AO;
    float* proj = buf + OFF_PROJ;
    float* o1   = buf + OFF_O1;
    float* f1   = buf + OFF_F1;
    float* f2   = buf + OFF_F2;   // 4 partials of ROWS*DD each

    scan_kernel<<<1, 32>>>(mask, idx);
    embed_kernel<<<ROWS, DD>>>(x, emb_W, emb_b, pos_enc, idx, use_pos, h);

    for (int l = 0; l < LL; l++) {
        const float* wW  = w_W   + (long long)l * DD * DD;
        const float* wB  = w_b   + l * DD;
        const float* oW  = out_W + (long long)l * DD * DD;
        const float* oB  = out_b + l * DD;
        const float* fW1 = ffn_W1 + (long long)l * DD * DFF;
        const float* fB1 = ffn_b1 + l * DFF;
        const float* fW2 = ffn_W2 + (long long)l * DFF * DD;
        const float* fB2 = ffn_b2 + l * DD;

        // qkv = h @ w_W[l] + w_b[l]            (512x256x256, 64 blocks)
        gemm_t<64,32><<<dim3(DD/32, ROWS/64, 1), 256>>>(
            h, wW, wB, qkv, ROWS, DD, DD, DD, 0, 0, 0, 0);
        // fused: qa = qkv@W1a ; qb = qkv@W1b   (z=2, 128 blocks)
        gemm_t<64,32><<<dim3(HH/32, ROWS/64, 2), 256>>>(
            qkv, nn_W1, nullptr, qa, ROWS, HH, DD, DD,
            0, (long long)DD * HH, (long long)ROWS * HH, 0);
        // s1[i,j] = sum_h w2*relu(qa_i + qb_j + b1)
        sim_kernel<<<dim3(SS/32, SS/32, BB), 64>>>(qa, qa + ROWS * HH, nn_b1, nn_W2, s1);
        // attn = softmax(s1 + s1^T + mask*-1e9)
        softmax_kernel<<<dim3(SS, BB), SS>>>(s1, mask, attn);
        // ao = attn @ qkv (batched over b)     (64 blocks)
        gemm_t<64,32><<<dim3(DD/32, SS/64, BB), 256>>>(
            attn, qkv, nullptr, ao, SS, DD, SS, SS,
            (long long)SS * SS, (long long)SS * DD, (long long)SS * DD, 0);
        // proj = ao @ out_W[l] + out_b[l]      (64 blocks)
        gemm_t<64,32><<<dim3(DD/32, ROWS/64, 1), 256>>>(
            ao, oW, oB, proj, ROWS, DD, DD, DD, 0, 0, 0, 0);
        // o1 = LN(h + proj)
        add_ln_kernel<<<ROWS, DD>>>(h, proj, 1, 0, ln1_g + l * DD, ln1_b + l * DD, o1);
        // f1 = relu(o1 @ ffn_W1 + ffn_b1)      (512x1024x256, 128 blocks)
        gemm_t<64,64><<<dim3(DFF/64, ROWS/64, 1), 256>>>(
            o1, fW1, fB1, f1, ROWS, DFF, DD, DD, 0, 0, 0, 1);
        // f2 partials: split-K x4 over DFF     (256 blocks); bias on z==0 partial
        gemm_t<64,32><<<dim3(DD/32, ROWS/64, 4), 256>>>(
            f1, fW2, fB2, f2, ROWS, DD, DFF/4, DFF,
            (long long)(DFF/4), (long long)(DFF/4) * DD, (long long)ROWS * DD, 0);
        // h = LN(o1 + sum_z f2_z)  (last layer -> d_out)
        float* dst = (l == LL - 1) ? out : h;
        add_ln_kernel<<<ROWS, DD>>>(o1, f2, 4, (long long)ROWS * DD,
                                    ln2_g + l * DD, ln2_b + l * DD, dst);
    }
}

// round 5
// speedup vs baseline: 1.6947x; 1.6947x over previous
#include <cuda_runtime.h>
#include <cuda_bf16.h>

// Problem constants
#define BB 2        // batch
#define SS 256      // seq
#define DD 256      // d_model
#define DFF 1024
#define HH 256      // hidden of pairwise MLP
#define LL 2        // layers
#define ROWS (BB*SS)   // 512

// ---------------- scratch (device globals; no allocation allowed) -------------
#define OFF_H     0
#define OFF_QKV   131072
#define OFF_QA    262144   /* qb = qa + ROWS*HH */
#define OFF_S1    524288
#define OFF_ATTN  655360
#define OFF_AO    786432
#define OFF_PROJ  917504
#define OFF_O1    1048576
#define OFF_F1    1179648  /* ROWS*DFF = 524288 */
#define OFF_F2    1703936  /* 4 split-K partials = 524288 */
#define BUF_TOTAL 2228224

__device__ float g_buf[BUF_TOTAL];

// ---------------- embedding: (bits@W + b)*16 + pos_enc[cumsum idx] ------------
// Per-block masked prefix reduction replaces a serial scan kernel:
// idx(b,s) = sum_{s'<=s} (1 - mask[b,s']), computed by a 256-wide block reduce.
__global__ __launch_bounds__(256) void embed_kernel(
    const int* __restrict__ x,
    const float* __restrict__ emb_W,
    const float* __restrict__ emb_b,
    const float* __restrict__ pos_enc,
    const float* __restrict__ mask,
    const int* __restrict__ use_pos,
    float* __restrict__ h)
{
    int bs = blockIdx.x;      // 0..511
    int b  = bs / SS;
    int s  = bs % SS;
    int d  = threadIdx.x;     // 0..255

    // prefix value for this (b, s): reduce thresholded mask row
    float contrib = (d <= s) ? (1.0f - mask[b * SS + d]) : 0.0f;
    __shared__ float red[8];
    float v = contrib;
    #pragma unroll
    for (int o = 16; o; o >>= 1) v += __shfl_xor_sync(0xffffffffu, v, o);
    if ((d & 31) == 0) red[d >> 5] = v;
    __syncthreads();
    float csum = red[0];
    #pragma unroll
    for (int w = 1; w < 8; w++) csum += red[w];
    int idx = (int)csum;

    int val = x[bs];
    float acc = emb_b[d];
    #pragma unroll
    for (int k = 0; k < 16; k++) {
        if ((val >> k) & 1) acc += emb_W[k * DD + d];
    }
    acc *= 16.0f;  // sqrt(256)
    if (use_pos[0]) acc += pos_enc[idx * DD + d];
    h[bs * DD + d] = acc;
}

// ---------------- double-buffered tiled GEMM ----------------------------------
// C = A(.. x K, lda) @ B(K x N) [+bias at z==bias_z] [relu]
// 256 threads, 16x16 thread grid, microtile (BM/16)x(BN/16), BK=32.
// z (blockIdx.z) applies element strides sA, sB, sC.
template<int BM, int BN, int BK>
__global__ __launch_bounds__(256) void gemm2(
    const float* __restrict__ A, const float* __restrict__ B,
    const float* __restrict__ bias, float* __restrict__ C,
    int N, int K, int lda,
    long long sA, long long sB, long long sC, int bias_z, int relu)
{
    constexpr int MI = BM / 16;
    constexpr int NI = BN / 16;
    constexpr int LA = BM * BK / 1024;   // float4 A-loads per thread
    constexpr int LB = BK * BN / 1024;   // float4 B-loads per thread
    constexpr int PAD = 2;

    __shared__ float As[2][BK][BM + PAD];   // transposed: As[k][m]
    __shared__ float Bs[2][BK][BN];

    int tid = threadIdx.x;
    int bm = blockIdx.y, bn = blockIdx.x, z = blockIdx.z;
    A += (long long)z * sA; B += (long long)z * sB; C += (long long)z * sC;
    int ty = tid >> 4, tx = tid & 15;

    int arow[LA], akq[LA];
    #pragma unroll
    for (int s = 0; s < LA; s++) {
        int idx = tid + s * 256;
        arow[s] = idx / (BK / 4);
        akq[s]  = (idx % (BK / 4)) * 4;
    }
    int brow[LB], bkq[LB];
    #pragma unroll
    for (int s = 0; s < LB; s++) {
        int idx = tid + s * 256;
        brow[s] = idx / (BN / 4);
        bkq[s]  = (idx % (BN / 4)) * 4;
    }

    float4 ra[LA], rb[LB];
    const float* Abase = A + (long long)(bm * BM) * lda;
    const float* Bbase = B + bn * BN;

    // prologue: load tile 0
    #pragma unroll
    for (int s = 0; s < LA; s++)
        ra[s] = *(const float4*)(Abase + (long long)arow[s] * lda + akq[s]);
    #pragma unroll
    for (int s = 0; s < LB; s++)
        rb[s] = *(const float4*)(Bbase + (long long)brow[s] * N + bkq[s]);
    #pragma unroll
    for (int s = 0; s < LA; s++) {
        As[0][akq[s] + 0][arow[s]] = ra[s].x;
        As[0][akq[s] + 1][arow[s]] = ra[s].y;
        As[0][akq[s] + 2][arow[s]] = ra[s].z;
        As[0][akq[s] + 3][arow[s]] = ra[s].w;
    }
    #pragma unroll
    for (int s = 0; s < LB; s++)
        *(float4*)&Bs[0][brow[s]][bkq[s]] = rb[s];
    __syncthreads();

    float acc[MI][NI];
    #pragma unroll
    for (int i = 0; i < MI; i++)
        #pragma unroll
        for (int j = 0; j < NI; j++) acc[i][j] = 0.f;

    int nt = K / BK;
    for (int t = 0; t < nt; t++) {
        int cur = t & 1;
        if (t + 1 < nt) {
            int kt = (t + 1) * BK;
            #pragma unroll
            for (int s = 0; s < LA; s++)
                ra[s] = *(const float4*)(Abase + (long long)arow[s] * lda + kt + akq[s]);
            #pragma unroll
            for (int s = 0; s < LB; s++)
                rb[s] = *(const float4*)(Bbase + (long long)(kt + brow[s]) * N + bkq[s]);
        }
        #pragma unroll
        for (int k = 0; k < BK; k++) {
            float av[MI], bv[NI];
            if constexpr (MI == 2) {
                float2 t2 = *(const float2*)&As[cur][k][ty * 2];
                av[0] = t2.x; av[1] = t2.y;
            } else {
                float4 t4 = *(const float4*)&As[cur][k][ty * 4];
                av[0] = t4.x; av[1] = t4.y; av[2] = t4.z; av[3] = t4.w;
            }
            if constexpr (NI == 2) {
                float2 t2 = *(const float2*)&Bs[cur][k][tx * 2];
                bv[0] = t2.x; bv[1] = t2.y;
            } else {
                float4 t4 = *(const float4*)&Bs[cur][k][tx * 4];
                bv[0] = t4.x; bv[1] = t4.y; bv[2] = t4.z; bv[3] = t4.w;
            }
            #pragma unroll
            for (int i = 0; i < MI; i++)
                #pragma unroll
                for (int j = 0; j < NI; j++)
                    acc[i][j] += av[i] * bv[j];
        }
        if (t + 1 < nt) {
            int nxt = cur ^ 1;
            #pragma unroll
            for (int s = 0; s < LA; s++) {
                As[nxt][akq[s] + 0][arow[s]] = ra[s].x;
                As[nxt][akq[s] + 1][arow[s]] = ra[s].y;
                As[nxt][akq[s] + 2][arow[s]] = ra[s].z;
                As[nxt][akq[s] + 3][arow[s]] = ra[s].w;
            }
            #pragma unroll
            for (int s = 0; s < LB; s++)
                *(float4*)&Bs[nxt][brow[s]][bkq[s]] = rb[s];
            __syncthreads();
        }
    }

    // epilogue
    float bvv[NI];
    #pragma unroll
    for (int j = 0; j < NI; j++) {
        int col = bn * BN + tx * NI + j;
        bvv[j] = (bias && z == bias_z) ? bias[col] : 0.f;
    }
    #pragma unroll
    for (int i = 0; i < MI; i++) {
        int row = bm * BM + ty * MI + i;
        float r[NI];
        #pragma unroll
        for (int j = 0; j < NI; j++) {
            r[j] = acc[i][j] + bvv[j];
            if (relu) r[j] = fmaxf(r[j], 0.f);
        }
        float* Cp = &C[(long long)row * N + bn * BN + tx * NI];
        if constexpr (NI == 2) {
            *(float2*)Cp = make_float2(r[0], r[1]);
        } else {
            *(float4*)Cp = make_float4(r[0], r[1], r[2], r[3]);
        }
    }
}

// ---------------- pairwise-MLP similarity -------------------------------------
// s1[i,j] = sum_h w2[h]*relu(qa[i,h]+qb[j,h])   (b1 pre-folded into qb)
// 256 threads, 32x32 tile, micro 2x2, grid (8,8,2) = 128 blocks.
__global__ __launch_bounds__(256) void sim_kernel(
    const float* __restrict__ qa, const float* __restrict__ qb,
    const float* __restrict__ w2, float* __restrict__ s1)
{
    __shared__ float Qa[32][34];
    __shared__ float Qb[32][34];
    __shared__ float Ws[HH];
    int tid = threadIdx.x;
    int b  = blockIdx.z;
    int i0 = blockIdx.y * 32;
    int j0 = blockIdx.x * 32;
    int ty = tid >> 4, tx = tid & 15;
    int r  = tid >> 3, kq = (tid & 7) << 2;

    Ws[tid] = w2[tid];

    float acc00 = 0.f, acc01 = 0.f, acc10 = 0.f, acc11 = 0.f;
    const float* Aq = qa + (long long)(b * SS + i0) * HH;
    const float* Bq = qb + (long long)(b * SS + j0) * HH;

    for (int hc = 0; hc < HH; hc += 32) {
        __syncthreads();
        float4 a4 = *(const float4*)(Aq + (long long)r * HH + hc + kq);
        float4 b4 = *(const float4*)(Bq + (long long)r * HH + hc + kq);
        Qa[kq + 0][r] = a4.x; Qa[kq + 1][r] = a4.y;
        Qa[kq + 2][r] = a4.z; Qa[kq + 3][r] = a4.w;
        Qb[kq + 0][r] = b4.x; Qb[kq + 1][r] = b4.y;
        Qb[kq + 2][r] = b4.z; Qb[kq + 3][r] = b4.w;
        __syncthreads();
        #pragma unroll
        for (int k = 0; k < 32; k++) {
            float w = Ws[hc + k];
            float2 a2 = *(const float2*)&Qa[k][ty * 2];
            float2 b2 = *(const float2*)&Qb[k][tx * 2];
            acc00 += w * fmaxf(a2.x + b2.x, 0.f);
            acc01 += w * fmaxf(a2.x + b2.y, 0.f);
            acc10 += w * fmaxf(a2.y + b2.x, 0.f);
            acc11 += w * fmaxf(a2.y + b2.y, 0.f);
        }
    }

    float* O = s1 + (long long)b * SS * SS;
    *(float2*)&O[(i0 + ty * 2 + 0) * SS + j0 + tx * 2] = make_float2(acc00, acc01);
    *(float2*)&O[(i0 + ty * 2 + 1) * SS + j0 + tx * 2] = make_float2(acc10, acc11);
}

// ---------------- softmax over (s1 + s1^T + mask*-1e9) ------------------------
// +2*nn_b2 is row-uniform -> cancels in softmax.
__global__ __launch_bounds__(256) void softmax_kernel(
    const float* __restrict__ s1, const float* __restrict__ mask,
    float* __restrict__ attn)
{
    int i = blockIdx.x, b = blockIdx.y, j = threadIdx.x;
    const float* S = s1 + (long long)b * SS * SS;
    float v = S[i * SS + j] + S[j * SS + i] + mask[b * SS + j] * -1e9f;

    __shared__ float red[8];
    float m = v;
    #pragma unroll
    for (int o = 16; o; o >>= 1) m = fmaxf(m, __shfl_xor_sync(0xffffffffu, m, o));
    if ((j & 31) == 0) red[j >> 5] = m;
    __syncthreads();
    m = red[0];
    #pragma unroll
    for (int w = 1; w < 8; w++) m = fmaxf(m, red[w]);

    float e = __expf(v - m);
    float s = e;
    #pragma unroll
    for (int o = 16; o; o >>= 1) s += __shfl_xor_sync(0xffffffffu, s, o);
    __syncthreads();
    if ((j & 31) == 0) red[j >> 5] = s;
    __syncthreads();
    s = red[0];
    #pragma unroll
    for (int w = 1; w < 8; w++) s += red[w];

    attn[(long long)b * SS * SS + i * SS + j] = e / s;
}

// ---------------- residual add (+ split-K partial sum) + layernorm ------------
__global__ __launch_bounds__(256) void add_ln_kernel(
    const float* __restrict__ x, const float* __restrict__ y,
    int nparts, long long pstride,
    const float* __restrict__ g, const float* __restrict__ bt,
    float* __restrict__ out)
{
    int row = blockIdx.x, t = threadIdx.x;
    long long e = (long long)row * DD + t;
    float v = x[e];
    for (int p = 0; p < nparts; p++) v += y[p * pstride + e];

    __shared__ float red[8];
    float s = v;
    #pragma unroll
    for (int o = 16; o; o >>= 1) s += __shfl_xor_sync(0xffffffffu, s, o);
    if ((t & 31) == 0) red[t >> 5] = s;
    __syncthreads();
    s = red[0];
    #pragma unroll
    for (int w = 1; w < 8; w++) s += red[w];
    float mu = s * (1.0f / DD);

    float d = v - mu;
    float q = d * d;
    #pragma unroll
    for (int o = 16; o; o >>= 1) q += __shfl_xor_sync(0xffffffffu, q, o);
    __syncthreads();
    if ((t & 31) == 0) red[t >> 5] = q;
    __syncthreads();
    q = red[0];
    #pragma unroll
    for (int w = 1; w < 8; w++) q += red[w];
    float var = q * (1.0f / DD);

    out[e] = d * rsqrtf(var + 1e-6f) * g[t] + bt[t];
}

// ---------------- host orchestration ------------------------------------------
extern "C" void kernel_launch(void* const* d_in, const int* in_sizes, int n_in,
                              void* d_out, int out_size) {
    const int*   x       = (const int*)d_in[0];
    const float* mask    = (const float*)d_in[1];
    const int*   use_pos = (const int*)d_in[3];
    const float* pos_enc = (const float*)d_in[4];
    const float* emb_W   = (const float*)d_in[5];
    const float* emb_b   = (const float*)d_in[6];
    const float* nn_W1   = (const float*)d_in[7];
    const float* nn_b1   = (const float*)d_in[8];
    const float* nn_W2   = (const float*)d_in[9];
    const float* w_W     = (const float*)d_in[11];
    const float* w_b     = (const float*)d_in[12];
    const float* out_W   = (const float*)d_in[13];
    const float* out_b   = (const float*)d_in[14];
    const float* ffn_W1  = (const float*)d_in[15];
    const float* ffn_b1  = (const float*)d_in[16];
    const float* ffn_W2  = (const float*)d_in[17];
    const float* ffn_b2  = (const float*)d_in[18];
    const float* ln1_g   = (const float*)d_in[19];
    const float* ln1_b   = (const float*)d_in[20];
    const float* ln2_g   = (const float*)d_in[21];
    const float* ln2_b   = (const float*)d_in[22];
    float* out = (float*)d_out;

    float* buf = nullptr;
    cudaGetSymbolAddress((void**)&buf, g_buf);

    float* h    = buf + OFF_H;
    float* qkv  = buf + OFF_QKV;
    float* qa   = buf + OFF_QA;   // qb = qa + ROWS*HH
    float* s1   = buf + OFF_S1;
    float* attn = buf + OFF_ATTN;
    float* ao   = buf + OFF_AO;
    float* proj = buf + OFF_PROJ;
    float* o1   = buf + OFF_O1;
    float* f1   = buf + OFF_F1;
    float* f2   = buf + OFF_F2;   // 4 partials of ROWS*DD each

    embed_kernel<<<ROWS, DD>>>(x, emb_W, emb_b, pos_enc, mask, use_pos, h);

    for (int l = 0; l < LL; l++) {
        const float* wW  = w_W   + (long long)l * DD * DD;
        const float* wB  = w_b   + l * DD;
        const float* oW  = out_W + (long long)l * DD * DD;
        const float* oB  = out_b + l * DD;
        const float* fW1 = ffn_W1 + (long long)l * DD * DFF;
        const float* fB1 = ffn_b1 + l * DFF;
        const float* fW2 = ffn_W2 + (long long)l * DFF * DD;
        const float* fB2 = ffn_b2 + l * DD;

        // qkv = h @ w_W[l] + w_b[l]      (grid 8x16 = 128 blocks)
        gemm2<32,32,32><<<dim3(DD/32, ROWS/32, 1), 256>>>(
            h, wW, wB, qkv, DD, DD, DD, 0, 0, 0, 0, 0);
        // fused: z=0 -> qa = qkv@W1a ; z=1 -> qb = qkv@W1b + b1   (256 blocks)
        gemm2<32,32,32><<<dim3(HH/32, ROWS/32, 2), 256>>>(
            qkv, nn_W1, nn_b1, qa, HH, DD, DD,
            0, (long long)DD * HH, (long long)ROWS * HH, /*bias_z=*/1, 0);
        // s1[i,j] = sum_h w2*relu(qa_i + qb_j)
        sim_kernel<<<dim3(SS/32, SS/32, BB), 256>>>(qa, qa + ROWS * HH, nn_W2, s1);
        // attn = softmax(s1 + s1^T + mask*-1e9)
        softmax_kernel<<<dim3(SS, BB), SS>>>(s1, mask, attn);
        // ao = attn @ qkv (batched over b)   (grid 8x8x2 = 128 blocks)
        gemm2<32,32,32><<<dim3(DD/32, SS/32, BB), 256>>>(
            attn, qkv, nullptr, ao, DD, SS, SS,
            (long long)SS * SS, (long long)SS * DD, (long long)SS * DD, 0, 0);
        // proj = ao @ out_W[l] + out_b[l]   (128 blocks)
        gemm2<32,32,32><<<dim3(DD/32, ROWS/32, 1), 256>>>(
            ao, oW, oB, proj, DD, DD, DD, 0, 0, 0, 0, 0);
        // o1 = LN(h + proj)
        add_ln_kernel<<<ROWS, DD>>>(h, proj, 1, 0, ln1_g + l * DD, ln1_b + l * DD, o1);
        // f1 = relu(o1 @ ffn_W1 + ffn_b1)   (grid 16x16 = 256 blocks)
        gemm2<32,64,32><<<dim3(DFF/64, ROWS/32, 1), 256>>>(
            o1, fW1, fB1, f1, DFF, DD, DD, 0, 0, 0, 0, 1);
        // f2 partials: split-K x4 over DFF  (grid 8x16x4 = 512 blocks)
        gemm2<32,32,32><<<dim3(DD/32, ROWS/32, 4), 256>>>(
            f1, fW2, fB2, f2, DD, DFF/4, DFF,
            (long long)(DFF/4), (long long)(DFF/4) * DD, (long long)ROWS * DD, 0, 0);
        // h = LN(o1 + sum_z f2_z)  (last layer -> d_out)
        float* dst = (l == LL - 1) ? out : h;
        add_ln_kernel<<<ROWS, DD>>>(o1, f2, 4, (long long)ROWS * DD,
                                    ln2_g + l * DD, ln2_b + l * DD, dst);
    }
}

// round 7
// speedup vs baseline: 1.6954x; 1.0004x over previous
#include <cuda_runtime.h>
#include <cuda_bf16.h>

// Problem constants
#define BB 2        // batch
#define SS 256      // seq
#define DD 256      // d_model
#define DFF 1024
#define HH 256      // hidden of pairwise MLP
#define LL 2        // layers
#define ROWS (BB*SS)   // 512

// ---------------- scratch (device globals; no allocation allowed) -------------
#define OFF_H     0
#define OFF_QKV   131072
#define OFF_QA    262144   /* qb = qa + ROWS*HH; ends 524288 */
#define OFF_S1    524288   /* 2 split-H partials: 2*131072;  ends 786432 */
#define OFF_ATTN  786432
#define OFF_AO    917504
#define OFF_PROJ  1048576
#define OFF_O1    1179648
#define OFF_F1    1310720  /* ROWS*DFF = 524288; ends 1835008 */
#define OFF_F2    1835008  /* 4 split-K partials = 524288; ends 2359296 */
#define BUF_TOTAL 2359296

__device__ float g_buf[BUF_TOTAL];

// ---------------- embedding: (bits@W + b)*16 + pos_enc[cumsum idx] ------------
__global__ __launch_bounds__(256) void embed_kernel(
    const int* __restrict__ x,
    const float* __restrict__ emb_W,
    const float* __restrict__ emb_b,
    const float* __restrict__ pos_enc,
    const float* __restrict__ mask,
    const int* __restrict__ use_pos,
    float* __restrict__ h)
{
    int bs = blockIdx.x;      // 0..511
    int b  = bs / SS;
    int s  = bs % SS;
    int d  = threadIdx.x;     // 0..255

    // prefix value for this (b, s): reduce thresholded mask row
    float contrib = (d <= s) ? (1.0f - mask[b * SS + d]) : 0.0f;
    __shared__ float red[8];
    float v = contrib;
    #pragma unroll
    for (int o = 16; o; o >>= 1) v += __shfl_xor_sync(0xffffffffu, v, o);
    if ((d & 31) == 0) red[d >> 5] = v;
    __syncthreads();
    float csum = red[0];
    #pragma unroll
    for (int w = 1; w < 8; w++) csum += red[w];
    int idx = (int)csum;

    int val = x[bs];
    float acc = emb_b[d];
    #pragma unroll
    for (int k = 0; k < 16; k++) {
        if ((val >> k) & 1) acc += emb_W[k * DD + d];
    }
    acc *= 16.0f;  // sqrt(256)
    if (use_pos[0]) acc += pos_enc[idx * DD + d];
    h[bs * DD + d] = acc;
}

// ---------------- double-buffered tiled GEMM ----------------------------------
// C = A(.. x K, lda) @ B(K x N) [+bias at z==bias_z] [relu]
// 256 threads, 16x16 thread grid, microtile (BM/16)x(BN/16).
// z (blockIdx.z) applies element strides sA, sB, sC.
template<int BM, int BN, int BK>
__global__ __launch_bounds__(256) void gemm2(
    const float* __restrict__ A, const float* __restrict__ B,
    const float* __restrict__ bias, float* __restrict__ C,
    int N, int K, int lda,
    long long sA, long long sB, long long sC, int bias_z, int relu)
{
    constexpr int MI = BM / 16;
    constexpr int NI = BN / 16;
    constexpr int LA = BM * BK / 1024;   // float4 A-loads per thread
    constexpr int LB = BK * BN / 1024;   // float4 B-loads per thread
    constexpr int PAD = 2;

    __shared__ float As[2][BK][BM + PAD];   // transposed: As[k][m]
    __shared__ float Bs[2][BK][BN];

    int tid = threadIdx.x;
    int bm = blockIdx.y, bn = blockIdx.x, z = blockIdx.z;
    A += (long long)z * sA; B += (long long)z * sB; C += (long long)z * sC;
    int ty = tid >> 4, tx = tid & 15;

    int arow[LA], akq[LA];
    #pragma unroll
    for (int s = 0; s < LA; s++) {
        int idx = tid + s * 256;
        arow[s] = idx / (BK / 4);
        akq[s]  = (idx % (BK / 4)) * 4;
    }
    int brow[LB], bkq[LB];
    #pragma unroll
    for (int s = 0; s < LB; s++) {
        int idx = tid + s * 256;
        brow[s] = idx / (BN / 4);
        bkq[s]  = (idx % (BN / 4)) * 4;
    }

    float4 ra[LA], rb[LB];
    const float* Abase = A + (long long)(bm * BM) * lda;
    const float* Bbase = B + bn * BN;

    // prologue: load tile 0
    #pragma unroll
    for (int s = 0; s < LA; s++)
        ra[s] = *(const float4*)(Abase + (long long)arow[s] * lda + akq[s]);
    #pragma unroll
    for (int s = 0; s < LB; s++)
        rb[s] = *(const float4*)(Bbase + (long long)brow[s] * N + bkq[s]);
    #pragma unroll
    for (int s = 0; s < LA; s++) {
        As[0][akq[s] + 0][arow[s]] = ra[s].x;
        As[0][akq[s] + 1][arow[s]] = ra[s].y;
        As[0][akq[s] + 2][arow[s]] = ra[s].z;
        As[0][akq[s] + 3][arow[s]] = ra[s].w;
    }
    #pragma unroll
    for (int s = 0; s < LB; s++)
        *(float4*)&Bs[0][brow[s]][bkq[s]] = rb[s];
    __syncthreads();

    float acc[MI][NI];
    #pragma unroll
    for (int i = 0; i < MI; i++)
        #pragma unroll
        for (int j = 0; j < NI; j++) acc[i][j] = 0.f;

    int nt = K / BK;
    for (int t = 0; t < nt; t++) {
        int cur = t & 1;
        if (t + 1 < nt) {
            int kt = (t + 1) * BK;
            #pragma unroll
            for (int s = 0; s < LA; s++)
                ra[s] = *(const float4*)(Abase + (long long)arow[s] * lda + kt + akq[s]);
            #pragma unroll
            for (int s = 0; s < LB; s++)
                rb[s] = *(const float4*)(Bbase + (long long)(kt + brow[s]) * N + bkq[s]);
        }
        #pragma unroll
        for (int k = 0; k < BK; k++) {
            float av[MI], bv[NI];
            if constexpr (MI == 2) {
                float2 t2 = *(const float2*)&As[cur][k][ty * 2];
                av[0] = t2.x; av[1] = t2.y;
            } else {
                float4 t4 = *(const float4*)&As[cur][k][ty * 4];
                av[0] = t4.x; av[1] = t4.y; av[2] = t4.z; av[3] = t4.w;
            }
            if constexpr (NI == 2) {
                float2 t2 = *(const float2*)&Bs[cur][k][tx * 2];
                bv[0] = t2.x; bv[1] = t2.y;
            } else {
                float4 t4 = *(const float4*)&Bs[cur][k][tx * 4];
                bv[0] = t4.x; bv[1] = t4.y; bv[2] = t4.z; bv[3] = t4.w;
            }
            #pragma unroll
            for (int i = 0; i < MI; i++)
                #pragma unroll
                for (int j = 0; j < NI; j++)
                    acc[i][j] += av[i] * bv[j];
        }
        if (t + 1 < nt) {
            int nxt = cur ^ 1;
            #pragma unroll
            for (int s = 0; s < LA; s++) {
                As[nxt][akq[s] + 0][arow[s]] = ra[s].x;
                As[nxt][akq[s] + 1][arow[s]] = ra[s].y;
                As[nxt][akq[s] + 2][arow[s]] = ra[s].z;
                As[nxt][akq[s] + 3][arow[s]] = ra[s].w;
            }
            #pragma unroll
            for (int s = 0; s < LB; s++)
                *(float4*)&Bs[nxt][brow[s]][bkq[s]] = rb[s];
            __syncthreads();
        }
    }

    // epilogue
    float bvv[NI];
    #pragma unroll
    for (int j = 0; j < NI; j++) {
        int col = bn * BN + tx * NI + j;
        bvv[j] = (bias && z == bias_z) ? bias[col] : 0.f;
    }
    #pragma unroll
    for (int i = 0; i < MI; i++) {
        int row = bm * BM + ty * MI + i;
        float r[NI];
        #pragma unroll
        for (int j = 0; j < NI; j++) {
            r[j] = acc[i][j] + bvv[j];
            if (relu) r[j] = fmaxf(r[j], 0.f);
        }
        float* Cp = &C[(long long)row * N + bn * BN + tx * NI];
        if constexpr (NI == 2) {
            *(float2*)Cp = make_float2(r[0], r[1]);
        } else {
            *(float4*)Cp = make_float4(r[0], r[1], r[2], r[3]);
        }
    }
}

// ---------------- pairwise-MLP similarity, split-H x2 -------------------------
// partial[half][b][i][j] = sum_{h in half} w2[h]*relu(qa[i,h]+qb[j,h])
// blockIdx.z = b + BB*half. Grid (8,8,4) = 256 blocks, 256 threads, 2x2 micro.
__global__ __launch_bounds__(256) void sim_kernel(
    const float* __restrict__ qa, const float* __restrict__ qb,
    const float* __restrict__ w2, float* __restrict__ s1)
{
    __shared__ float Qa[32][34];
    __shared__ float Qb[32][34];
    __shared__ float Ws[HH / 2];
    int tid = threadIdx.x;
    int zb   = blockIdx.z;
    int b    = zb & (BB - 1);
    int half = zb >> 1;          // 0 or 1
    int h0   = half * (HH / 2);
    int i0 = blockIdx.y * 32;
    int j0 = blockIdx.x * 32;
    int ty = tid >> 4, tx = tid & 15;
    int r  = tid >> 3, kq = (tid & 7) << 2;

    if (tid < HH / 2) Ws[tid] = w2[h0 + tid];

    float acc00 = 0.f, acc01 = 0.f, acc10 = 0.f, acc11 = 0.f;
    const float* Aq = qa + (long long)(b * SS + i0) * HH + h0;
    const float* Bq = qb + (long long)(b * SS + j0) * HH + h0;

    for (int hc = 0; hc < HH / 2; hc += 32) {
        __syncthreads();
        float4 a4 = *(const float4*)(Aq + (long long)r * HH + hc + kq);
        float4 b4 = *(const float4*)(Bq + (long long)r * HH + hc + kq);
        Qa[kq + 0][r] = a4.x; Qa[kq + 1][r] = a4.y;
        Qa[kq + 2][r] = a4.z; Qa[kq + 3][r] = a4.w;
        Qb[kq + 0][r] = b4.x; Qb[kq + 1][r] = b4.y;
        Qb[kq + 2][r] = b4.z; Qb[kq + 3][r] = b4.w;
        __syncthreads();
        #pragma unroll
        for (int k = 0; k < 32; k++) {
            float w = Ws[hc + k];
            float2 a2 = *(const float2*)&Qa[k][ty * 2];
            float2 b2 = *(const float2*)&Qb[k][tx * 2];
            acc00 += w * fmaxf(a2.x + b2.x, 0.f);
            acc01 += w * fmaxf(a2.x + b2.y, 0.f);
            acc10 += w * fmaxf(a2.y + b2.x, 0.f);
            acc11 += w * fmaxf(a2.y + b2.y, 0.f);
        }
    }

    float* O = s1 + (long long)half * BB * SS * SS + (long long)b * SS * SS;
    *(float2*)&O[(i0 + ty * 2 + 0) * SS + j0 + tx * 2] = make_float2(acc00, acc01);
    *(float2*)&O[(i0 + ty * 2 + 1) * SS + j0 + tx * 2] = make_float2(acc10, acc11);
}

// ---------------- softmax over (P0 + P0^T + P1 + P1^T + mask*-1e9) ------------
// +2*nn_b2 is row-uniform -> cancels in softmax.
__global__ __launch_bounds__(256) void softmax_kernel(
    const float* __restrict__ s1, const float* __restrict__ mask,
    float* __restrict__ attn)
{
    int i = blockIdx.x, b = blockIdx.y, j = threadIdx.x;
    const float* P0 = s1 + (long long)b * SS * SS;
    const float* P1 = P0 + (long long)BB * SS * SS;
    float v = P0[i * SS + j] + P0[j * SS + i]
            + P1[i * SS + j] + P1[j * SS + i]
            + mask[b * SS + j] * -1e9f;

    __shared__ float red[8];
    float m = v;
    #pragma unroll
    for (int o = 16; o; o >>= 1) m = fmaxf(m, __shfl_xor_sync(0xffffffffu, m, o));
    if ((j & 31) == 0) red[j >> 5] = m;
    __syncthreads();
    m = red[0];
    #pragma unroll
    for (int w = 1; w < 8; w++) m = fmaxf(m, red[w]);

    float e = __expf(v - m);
    float s = e;
    #pragma unroll
    for (int o = 16; o; o >>= 1) s += __shfl_xor_sync(0xffffffffu, s, o);
    __syncthreads();
    if ((j & 31) == 0) red[j >> 5] = s;
    __syncthreads();
    s = red[0];
    #pragma unroll
    for (int w = 1; w < 8; w++) s += red[w];

    attn[(long long)b * SS * SS + i * SS + j] = e / s;
}

// ---------------- residual add (+ split-K partial sum) + layernorm ------------
__global__ __launch_bounds__(256) void add_ln_kernel(
    const float* __restrict__ x, const float* __restrict__ y,
    int nparts, long long pstride,
    const float* __restrict__ g, const float* __restrict__ bt,
    float* __restrict__ out)
{
    int row = blockIdx.x, t = threadIdx.x;
    long long e = (long long)row * DD + t;
    float v = x[e];
    for (int p = 0; p < nparts; p++) v += y[p * pstride + e];

    __shared__ float red[8];
    float s = v;
    #pragma unroll
    for (int o = 16; o; o >>= 1) s += __shfl_xor_sync(0xffffffffu, s, o);
    if ((t & 31) == 0) red[t >> 5] = s;
    __syncthreads();
    s = red[0];
    #pragma unroll
    for (int w = 1; w < 8; w++) s += red[w];
    float mu = s * (1.0f / DD);

    float d = v - mu;
    float q = d * d;
    #pragma unroll
    for (int o = 16; o; o >>= 1) q += __shfl_xor_sync(0xffffffffu, q, o);
    __syncthreads();
    if ((t & 31) == 0) red[t >> 5] = q;
    __syncthreads();
    q = red[0];
    #pragma unroll
    for (int w = 1; w < 8; w++) q += red[w];
    float var = q * (1.0f / DD);

    out[e] = d * rsqrtf(var + 1e-6f) * g[t] + bt[t];
}

// ---------------- host orchestration ------------------------------------------
extern "C" void kernel_launch(void* const* d_in, const int* in_sizes, int n_in,
                              void* d_out, int out_size) {
    const int*   x       = (const int*)d_in[0];
    const float* mask    = (const float*)d_in[1];
    const int*   use_pos = (const int*)d_in[3];
    const float* pos_enc = (const float*)d_in[4];
    const float* emb_W   = (const float*)d_in[5];
    const float* emb_b   = (const float*)d_in[6];
    const float* nn_W1   = (const float*)d_in[7];
    const float* nn_b1   = (const float*)d_in[8];
    const float* nn_W2   = (const float*)d_in[9];
    const float* w_W     = (const float*)d_in[11];
    const float* w_b     = (const float*)d_in[12];
    const float* out_W   = (const float*)d_in[13];
    const float* out_b   = (const float*)d_in[14];
    const float* ffn_W1  = (const float*)d_in[15];
    const float* ffn_b1  = (const float*)d_in[16];
    const float* ffn_W2  = (const float*)d_in[17];
    const float* ffn_b2  = (const float*)d_in[18];
    const float* ln1_g   = (const float*)d_in[19];
    const float* ln1_b   = (const float*)d_in[20];
    const float* ln2_g   = (const float*)d_in[21];
    const float* ln2_b   = (const float*)d_in[22];
    float* out = (float*)d_out;

    float* buf = nullptr;
    cudaGetSymbolAddress((void**)&buf, g_buf);

    float* h    = buf + OFF_H;
    float* qkv  = buf + OFF_QKV;
    float* qa   = buf + OFF_QA;   // qb = qa + ROWS*HH
    float* s1   = buf + OFF_S1;   // 2 split-H partials
    float* attn = buf + OFF_ATTN;
    float* ao   = buf + OFF_AO;
    float* proj = buf + OFF_PROJ;
    float* o1   = buf + OFF_O1;
    float* f1   = buf + OFF_F1;
    float* f2   = buf + OFF_F2;   // 4 partials of ROWS*DD each

    embed_kernel<<<ROWS, DD>>>(x, emb_W, emb_b, pos_enc, mask, use_pos, h);

    for (int l = 0; l < LL; l++) {
        const float* wW  = w_W   + (long long)l * DD * DD;
        const float* wB  = w_b   + l * DD;
        const float* oW  = out_W + (long long)l * DD * DD;
        const float* oB  = out_b + l * DD;
        const float* fW1 = ffn_W1 + (long long)l * DD * DFF;
        const float* fB1 = ffn_b1 + l * DFF;
        const float* fW2 = ffn_W2 + (long long)l * DFF * DD;
        const float* fB2 = ffn_b2 + l * DD;

        // qkv = h @ w_W[l] + w_b[l]      (grid 8x16 = 128 blocks, BK=64)
        gemm2<32,32,64><<<dim3(DD/32, ROWS/32, 1), 256>>>(
            h, wW, wB, qkv, DD, DD, DD, 0, 0, 0, 0, 0);
        // fused: z=0 -> qa = qkv@W1a ; z=1 -> qb = qkv@W1b + b1   (256 blocks)
        gemm2<32,32,64><<<dim3(HH/32, ROWS/32, 2), 256>>>(
            qkv, nn_W1, nn_b1, qa, HH, DD, DD,
            0, (long long)DD * HH, (long long)ROWS * HH, /*bias_z=*/1, 0);
        // s1 partials (split-H x2): grid (8,8,4) = 256 blocks
        sim_kernel<<<dim3(SS/32, SS/32, BB * 2), 256>>>(qa, qa + ROWS * HH, nn_W2, s1);
        // attn = softmax(P0 + P0^T + P1 + P1^T + mask*-1e9)
        softmax_kernel<<<dim3(SS, BB), SS>>>(s1, mask, attn);
        // ao = attn @ qkv (batched over b)   (grid 8x8x2 = 128 blocks)
        gemm2<32,32,64><<<dim3(DD/32, SS/32, BB), 256>>>(
            attn, qkv, nullptr, ao, DD, SS, SS,
            (long long)SS * SS, (long long)SS * DD, (long long)SS * DD, 0, 0);
        // proj = ao @ out_W[l] + out_b[l]   (128 blocks)
        gemm2<32,32,64><<<dim3(DD/32, ROWS/32, 1), 256>>>(
            ao, oW, oB, proj, DD, DD, DD, 0, 0, 0, 0, 0);
        // o1 = LN(h + proj)
        add_ln_kernel<<<ROWS, DD>>>(h, proj, 1, 0, ln1_g + l * DD, ln1_b + l * DD, o1);
        // f1 = relu(o1 @ ffn_W1 + ffn_b1)   (grid 16x16 = 256 blocks; BK=32 for smem)
        gemm2<32,64,32><<<dim3(DFF/64, ROWS/32, 1), 256>>>(
            o1, fW1, fB1, f1, DFF, DD, DD, 0, 0, 0, 0, 1);
        // f2 partials: split-K x4 over DFF  (grid 8x16x4 = 512 blocks, BK=64)
        gemm2<32,32,64><<<dim3(DD/32, ROWS/32, 4), 256>>>(
            f1, fW2, fB2, f2, DD, DFF/4, DFF,
            (long long)(DFF/4), (long long)(DFF/4) * DD, (long long)ROWS * DD, 0, 0);
        // h = LN(o1 + sum_z f2_z)  (last layer -> d_out)
        float* dst = (l == LL - 1) ? out : h;
        add_ln_kernel<<<ROWS, DD>>>(o1, f2, 4, (long long)ROWS * DD,
                                    ln2_g + l * DD, ln2_b + l * DD, dst);
    }
}